// round 1
// baseline (speedup 1.0000x reference)
#include <cuda_runtime.h>

// Problem constants (B=2, T=2048 -> N=4096 tokens)
#define NTOK 4096
#define DDIM 1024
#define HDIM 4096
#define NEXP 8
#define NSLOT (NTOK * 2)   // total (token, expert) assignments, top-2

// ---------------- scratch (static device globals; no allocation) ------------
__device__ float g_h[(size_t)NSLOT * HDIM];    // relu(x Wfc^T)^2, slot-major  (134 MB)
__device__ float g_yp[(size_t)NSLOT * DDIM];   // per-assignment proj output   (33 MB)
__device__ int   g_eidx[NSLOT];                // expert index per (token,k)
__device__ float g_ew[NSLOT];                  // renormalized routing weight
__device__ int   g_pos[NSLOT];                 // position within expert
__device__ int   g_slotof[NSLOT];              // global slot per (token,k)
__device__ int   g_perm[NSLOT];                // slot -> token
__device__ int   g_cnt[NEXP];
__device__ int   g_base[NEXP];
__device__ float g_sump[NEXP];
__device__ float g_loss;

// ---------------- init -------------------------------------------------------
__global__ void init_kernel() {
    int t = threadIdx.x;
    if (t < NEXP) { g_cnt[t] = 0; g_sump[t] = 0.0f; }
}

// ---------------- gating: 1 warp per token -----------------------------------
__global__ void gating_kernel(const float* __restrict__ x,
                              const float* __restrict__ wg) {
    int warp = (blockIdx.x * blockDim.x + threadIdx.x) >> 5;
    int lane = threadIdx.x & 31;
    if (warp >= NTOK) return;
    const float* xr = x + (size_t)warp * DDIM;

    float acc[NEXP];
#pragma unroll
    for (int e = 0; e < NEXP; e++) acc[e] = 0.0f;

    for (int d = lane; d < DDIM; d += 32) {
        float xv = xr[d];
#pragma unroll
        for (int e = 0; e < NEXP; e++) acc[e] += xv * wg[e * DDIM + d];
    }
#pragma unroll
    for (int e = 0; e < NEXP; e++) {
#pragma unroll
        for (int o = 16; o > 0; o >>= 1)
            acc[e] += __shfl_xor_sync(0xFFFFFFFFu, acc[e], o);
    }

    if (lane == 0) {
        // softmax over 8 logits
        float mx = acc[0];
#pragma unroll
        for (int e = 1; e < NEXP; e++) mx = fmaxf(mx, acc[e]);
        float p[NEXP], s = 0.0f;
#pragma unroll
        for (int e = 0; e < NEXP; e++) { p[e] = __expf(acc[e] - mx); s += p[e]; }
        float inv = 1.0f / s;
#pragma unroll
        for (int e = 0; e < NEXP; e++) p[e] *= inv;

#pragma unroll
        for (int e = 0; e < NEXP; e++) atomicAdd(&g_sump[e], p[e]);

        // top-2, ties -> lowest index (matches lax.top_k)
        int i0 = 0;
#pragma unroll
        for (int e = 1; e < NEXP; e++) if (p[e] > p[i0]) i0 = e;
        int i1 = (i0 == 0) ? 1 : 0;
#pragma unroll
        for (int e = 0; e < NEXP; e++) if (e != i0 && p[e] > p[i1]) i1 = e;

        float w0 = p[i0], w1 = p[i1];
        float rinv = 1.0f / (w0 + w1);
        w0 *= rinv; w1 *= rinv;

        g_eidx[2 * warp + 0] = i0;
        g_eidx[2 * warp + 1] = i1;
        g_ew[2 * warp + 0] = w0;
        g_ew[2 * warp + 1] = w1;
        g_pos[2 * warp + 0] = atomicAdd(&g_cnt[i0], 1);
        g_pos[2 * warp + 1] = atomicAdd(&g_cnt[i1], 1);
    }
}

// ---------------- prefix + balance loss --------------------------------------
__global__ void prefix_kernel() {
    if (threadIdx.x == 0) {
        int b = 0;
        float loss = 0.0f;
        for (int e = 0; e < NEXP; e++) {
            g_base[e] = b;
            b += g_cnt[e];
            loss += g_sump[e] * (float)g_cnt[e];
        }
        g_loss = loss * (float)NEXP / ((float)NTOK * (float)NTOK);
    }
}

// ---------------- scatter: build slot permutation ----------------------------
__global__ void scatter_kernel() {
    int t = blockIdx.x * blockDim.x + threadIdx.x;
    if (t < NSLOT) {
        int e = g_eidx[t];
        int slot = g_base[e] + g_pos[t];
        g_slotof[t] = slot;
        g_perm[slot] = t >> 1;   // token index
    }
}

// ---------------- grouped tiled SGEMM ----------------------------------------
// PH1: C[slot, n] = relu( x[perm[slot],:] . Wfc[e][n,:] )^2   (KD=D, ND=H)
// PH2: C[slot, n] = g_h[slot,:] . Wproj[e][n,:]               (KD=H, ND=D)
#define BM 128
#define BN 128
#define BK 8

template <int KD, int ND, bool PH1>
__global__ __launch_bounds__(256, 2)
void gemm_kernel(const float* __restrict__ Ain,
                 const float* __restrict__ W) {
    int e = blockIdx.z;
    int count = g_cnt[e];
    int m0 = blockIdx.y * BM;
    if (m0 >= count) return;
    int n0 = blockIdx.x * BN;
    int base = g_base[e];

    const float* A = PH1 ? Ain : (const float*)g_h;
    const float* B = W + (size_t)e * (size_t)KD * (size_t)ND;

    __shared__ float As[BK][BM + 4];
    __shared__ float Bs[BK][BN + 4];

    int tid = threadIdx.x;          // 0..255
    int tx = tid & 15;              // 0..15
    int ty = tid >> 4;              // 0..15

    int lr = tid >> 1;              // tile row for loads, 0..127
    int lk = (tid & 1) * 4;         // 0 or 4

    int am = m0 + lr;
    bool avalid = am < count;
    const float* arow = nullptr;
    if (avalid) {
        int g = PH1 ? g_perm[base + am] : (base + am);
        arow = A + (size_t)g * KD;
    }
    const float* brow = B + (size_t)(n0 + lr) * KD;

    float acc[8][8];
#pragma unroll
    for (int i = 0; i < 8; i++)
#pragma unroll
        for (int j = 0; j < 8; j++) acc[i][j] = 0.0f;

    for (int k0 = 0; k0 < KD; k0 += BK) {
        float4 av = avalid ? *(const float4*)(arow + k0 + lk)
                           : make_float4(0.f, 0.f, 0.f, 0.f);
        float4 bv = *(const float4*)(brow + k0 + lk);
        As[lk + 0][lr] = av.x; As[lk + 1][lr] = av.y;
        As[lk + 2][lr] = av.z; As[lk + 3][lr] = av.w;
        Bs[lk + 0][lr] = bv.x; Bs[lk + 1][lr] = bv.y;
        Bs[lk + 2][lr] = bv.z; Bs[lk + 3][lr] = bv.w;
        __syncthreads();

#pragma unroll
        for (int k = 0; k < BK; k++) {
            float af[8], bf[8];
#pragma unroll
            for (int i = 0; i < 8; i++) af[i] = As[k][ty * 8 + i];
#pragma unroll
            for (int j = 0; j < 8; j++) bf[j] = Bs[k][tx * 8 + j];
#pragma unroll
            for (int i = 0; i < 8; i++)
#pragma unroll
                for (int j = 0; j < 8; j++) acc[i][j] += af[i] * bf[j];
        }
        __syncthreads();
    }

    float* Cbuf = PH1 ? g_h : g_yp;
#pragma unroll
    for (int i = 0; i < 8; i++) {
        int m = m0 + ty * 8 + i;
        if (m < count) {
            int slot = base + m;
            float* crow = Cbuf + (size_t)slot * ND + n0 + tx * 8;
#pragma unroll
            for (int j = 0; j < 8; j++) {
                float v = acc[i][j];
                if (PH1) { v = fmaxf(v, 0.0f); v = v * v; }
                crow[j] = v;
            }
        }
    }
}

// ---------------- combine ----------------------------------------------------
__global__ void combine_kernel(float* __restrict__ out, int out_size) {
    const int nv = DDIM / 4;
    int t = blockIdx.x * blockDim.x + threadIdx.x;
    if (t < NTOK * nv) {
        int n = t / nv, dv = t % nv;
        int s0 = g_slotof[2 * n], s1 = g_slotof[2 * n + 1];
        float w0 = g_ew[2 * n], w1 = g_ew[2 * n + 1];
        const float4* yp = (const float4*)g_yp;
        float4 a = yp[(size_t)s0 * nv + dv];
        float4 b = yp[(size_t)s1 * nv + dv];
        float4 r;
        r.x = w0 * a.x + w1 * b.x;
        r.y = w0 * a.y + w1 * b.y;
        r.z = w0 * a.z + w1 * b.z;
        r.w = w0 * a.w + w1 * b.w;
        ((float4*)out)[t] = r;
    }
    if (t == 0) {
        for (int idx = NTOK * DDIM; idx < out_size; idx++) out[idx] = g_loss;
    }
}

// ---------------- launch -----------------------------------------------------
extern "C" void kernel_launch(void* const* d_in, const int* in_sizes, int n_in,
                              void* d_out, int out_size) {
    const float* x   = (const float*)d_in[0];
    const float* wg  = (const float*)d_in[1];
    const float* wfc = (const float*)d_in[2];
    const float* wpj = (const float*)d_in[3];
    float* out = (float*)d_out;

    init_kernel<<<1, 32>>>();
    gating_kernel<<<NTOK / 4, 128>>>(x, wg);
    prefix_kernel<<<1, 32>>>();
    scatter_kernel<<<(NSLOT + 255) / 256, 256>>>();

    dim3 g1(HDIM / BN, NTOK / BM, NEXP);   // 32 x 32 x 8
    gemm_kernel<DDIM, HDIM, true><<<g1, 256>>>(x, wfc);

    dim3 g2(DDIM / BN, NTOK / BM, NEXP);   // 8 x 32 x 8
    gemm_kernel<HDIM, DDIM, false><<<g2, 256>>>(x, wpj);

    combine_kernel<<<(NTOK * DDIM / 4 + 255) / 256, 256>>>(out, out_size);
}

// round 4
// speedup vs baseline: 1.4234x; 1.4234x over previous
#include <cuda_runtime.h>
#include <cuda_bf16.h>
#include <cstdint>

// Problem constants (B=2, T=2048 -> N=4096 tokens)
#define NTOK 4096
#define DDIM 1024
#define HDIM 4096
#define NEXP 8
#define NSLOT (NTOK * 2)

// ---------------- scratch (static device globals; no allocation) ------------
__device__ float g_h[(size_t)NSLOT * HDIM];    // relu(x Wfc^T)^2, slot-major
__device__ float g_yp[(size_t)NSLOT * DDIM];   // per-assignment proj output
__device__ int   g_eidx[NSLOT];
__device__ float g_ew[NSLOT];
__device__ int   g_pos[NSLOT];
__device__ int   g_slotof[NSLOT];
__device__ int   g_perm[NSLOT];
__device__ int   g_cnt[NEXP];
__device__ int   g_base[NEXP];
__device__ float g_sump[NEXP];
__device__ float g_loss;

// ---------------- init -------------------------------------------------------
__global__ void init_kernel() {
    int t = threadIdx.x;
    if (t < NEXP) { g_cnt[t] = 0; g_sump[t] = 0.0f; }
}

// ---------------- gating: 1 warp per token -----------------------------------
__global__ void gating_kernel(const float* __restrict__ x,
                              const float* __restrict__ wg) {
    int warp = (blockIdx.x * blockDim.x + threadIdx.x) >> 5;
    int lane = threadIdx.x & 31;
    if (warp >= NTOK) return;
    const float* xr = x + (size_t)warp * DDIM;

    float acc[NEXP];
#pragma unroll
    for (int e = 0; e < NEXP; e++) acc[e] = 0.0f;

    for (int d = lane; d < DDIM; d += 32) {
        float xv = xr[d];
#pragma unroll
        for (int e = 0; e < NEXP; e++) acc[e] += xv * wg[e * DDIM + d];
    }
#pragma unroll
    for (int e = 0; e < NEXP; e++) {
#pragma unroll
        for (int o = 16; o > 0; o >>= 1)
            acc[e] += __shfl_xor_sync(0xFFFFFFFFu, acc[e], o);
    }

    if (lane == 0) {
        float mx = acc[0];
#pragma unroll
        for (int e = 1; e < NEXP; e++) mx = fmaxf(mx, acc[e]);
        float p[NEXP], s = 0.0f;
#pragma unroll
        for (int e = 0; e < NEXP; e++) { p[e] = __expf(acc[e] - mx); s += p[e]; }
        float inv = 1.0f / s;
#pragma unroll
        for (int e = 0; e < NEXP; e++) p[e] *= inv;

#pragma unroll
        for (int e = 0; e < NEXP; e++) atomicAdd(&g_sump[e], p[e]);

        int i0 = 0;
#pragma unroll
        for (int e = 1; e < NEXP; e++) if (p[e] > p[i0]) i0 = e;
        int i1 = (i0 == 0) ? 1 : 0;
#pragma unroll
        for (int e = 0; e < NEXP; e++) if (e != i0 && p[e] > p[i1]) i1 = e;

        float w0 = p[i0], w1 = p[i1];
        float rinv = 1.0f / (w0 + w1);
        w0 *= rinv; w1 *= rinv;

        g_eidx[2 * warp + 0] = i0;
        g_eidx[2 * warp + 1] = i1;
        g_ew[2 * warp + 0] = w0;
        g_ew[2 * warp + 1] = w1;
        g_pos[2 * warp + 0] = atomicAdd(&g_cnt[i0], 1);
        g_pos[2 * warp + 1] = atomicAdd(&g_cnt[i1], 1);
    }
}

// ---------------- prefix + balance loss --------------------------------------
__global__ void prefix_kernel() {
    if (threadIdx.x == 0) {
        int b = 0;
        float loss = 0.0f;
        for (int e = 0; e < NEXP; e++) {
            g_base[e] = b;
            b += g_cnt[e];
            loss += g_sump[e] * (float)g_cnt[e];
        }
        g_loss = loss * (float)NEXP / ((float)NTOK * (float)NTOK);
    }
}

// ---------------- scatter ----------------------------------------------------
__global__ void scatter_kernel() {
    int t = blockIdx.x * blockDim.x + threadIdx.x;
    if (t < NSLOT) {
        int e = g_eidx[t];
        int slot = g_base[e] + g_pos[t];
        g_slotof[t] = slot;
        g_perm[slot] = t >> 1;
    }
}

// ---------------- bf16x3 mma.sync grouped GEMM -------------------------------
// D[m,n] = sum_k A[m,k]*B[n,k].  fp32 emulation: v = hi + lo (bf16 each),
// acc += Ahi*Bhi + Alo*Bhi + Ahi*Blo  (error ~2^-17 relative).
// CTA tile 128x64, K chunk 32, 8 warps in 4(M) x 2(N), warp tile 32x32.
#define TM 128
#define TN 64
#define TKC 32
#define SROW 40                    // halves per smem row (80B, conflict-free)
#define AHI_OFF 0
#define ALO_OFF 10240              // 128*40*2
#define BHI_OFF 20480
#define BLO_OFF 25600              // +64*40*2
#define SMEM_BYTES 30720

__device__ __forceinline__ uint32_t smem_u32(const void* p) {
    uint32_t a;
    asm("{ .reg .u64 t; cvta.to.shared.u64 t, %1; cvt.u32.u64 %0, t; }"
        : "=r"(a) : "l"(p));
    return a;
}

// pack two fp32 -> bf16x2 (x -> low half, y -> high half)
__device__ __forceinline__ uint32_t pack2(float x, float y) {
    uint32_t r;
    asm("cvt.rn.bf16x2.f32 %0, %1, %2;" : "=r"(r) : "f"(y), "f"(x));
    return r;
}

__device__ __forceinline__ void split4(float4 v, uint2& hi, uint2& lo) {
    uint32_t h0 = pack2(v.x, v.y);
    uint32_t h1 = pack2(v.z, v.w);
    float hx = __uint_as_float(h0 << 16);
    float hy = __uint_as_float(h0 & 0xFFFF0000u);
    float hz = __uint_as_float(h1 << 16);
    float hw = __uint_as_float(h1 & 0xFFFF0000u);
    hi.x = h0; hi.y = h1;
    lo.x = pack2(v.x - hx, v.y - hy);
    lo.y = pack2(v.z - hz, v.w - hw);
}

#define LDSM4(r, addr) \
    asm volatile("ldmatrix.sync.aligned.m8n8.x4.shared.b16 {%0,%1,%2,%3}, [%4];" \
                 : "=r"((r)[0]), "=r"((r)[1]), "=r"((r)[2]), "=r"((r)[3]) \
                 : "r"(addr))

#define MMA16816(c, a, b0_, b1_) \
    asm volatile("mma.sync.aligned.m16n8k16.row.col.f32.bf16.bf16.f32 " \
                 "{%0,%1,%2,%3}, {%4,%5,%6,%7}, {%8,%9}, {%0,%1,%2,%3};" \
                 : "+f"((c)[0]), "+f"((c)[1]), "+f"((c)[2]), "+f"((c)[3]) \
                 : "r"((a)[0]), "r"((a)[1]), "r"((a)[2]), "r"((a)[3]), \
                   "r"(b0_), "r"(b1_))

template <int KD, int ND, bool PH1>
__global__ __launch_bounds__(256, 2)
void gemm_mma(const float* __restrict__ Ain, const float* __restrict__ W) {
    __shared__ __align__(16) unsigned char smem[SMEM_BYTES];
    int e = blockIdx.z;
    int count = g_cnt[e];
    int m0 = blockIdx.y * TM;
    if (m0 >= count) return;
    int n0 = blockIdx.x * TN;
    int base = g_base[e];

    const float* A = PH1 ? Ain : (const float*)g_h;
    const float* B = W + (size_t)e * KD * ND;

    int tid = threadIdx.x;
    int lane = tid & 31;
    int wid = tid >> 5;
    int warp_m = wid & 3;
    int warp_n = wid >> 2;

    uint32_t sb = smem_u32(smem);

    // --- loader indices ---
    int lrow = tid >> 1;                 // A tile row 0..127
    int lcA = (tid & 1) * 16;            // A float col 0/16
    int brow = tid >> 2;                 // B tile row 0..63
    int bcol = (tid & 3) * 8;            // B float col 0/8/16/24

    int am = m0 + lrow;
    bool av = am < count;
    const float* arow_p = nullptr;
    if (av) {
        int gidx = PH1 ? g_perm[base + am] : (base + am);
        arow_p = A + (size_t)gidx * KD + lcA;
    }
    const float* brow_p = B + (size_t)(n0 + brow) * KD + bcol;

    int aoffb = lrow * (SROW * 2) + lcA * 2;   // byte offset in A smem tiles
    int boffb = brow * (SROW * 2) + bcol * 2;

    // --- ldmatrix lane addresses ---
    uint32_t arow_l = (uint32_t)(warp_m * 32 + (lane & 7) + ((lane >> 3) & 1) * 8);
    uint32_t akoff = (uint32_t)((lane >> 4) * 8);
    uint32_t a_ld = sb + AHI_OFF + (arow_l * SROW + akoff) * 2;
    uint32_t brow_l = (uint32_t)(warp_n * 32 + (lane & 7) + (lane >> 4) * 8);
    uint32_t bkoff = (uint32_t)(((lane >> 3) & 1) * 8);
    uint32_t b_ld = sb + BHI_OFF + (brow_l * SROW + bkoff) * 2;

    float acc[2][4][4];
#pragma unroll
    for (int i = 0; i < 2; i++)
#pragma unroll
        for (int j = 0; j < 4; j++)
#pragma unroll
            for (int q = 0; q < 4; q++) acc[i][j][q] = 0.0f;

    float4 ra[4], rb[2];
#pragma unroll
    for (int i = 0; i < 4; i++)
        ra[i] = av ? *(const float4*)(arow_p + 4 * i)
                   : make_float4(0.f, 0.f, 0.f, 0.f);
#pragma unroll
    for (int i = 0; i < 2; i++)
        rb[i] = *(const float4*)(brow_p + 4 * i);

    const int NCH = KD / TKC;
    for (int c = 0; c < NCH; c++) {
        // split & store current chunk
#pragma unroll
        for (int i = 0; i < 4; i++) {
            uint2 h, l;
            split4(ra[i], h, l);
            *(uint2*)(smem + AHI_OFF + aoffb + i * 8) = h;
            *(uint2*)(smem + ALO_OFF + aoffb + i * 8) = l;
        }
#pragma unroll
        for (int i = 0; i < 2; i++) {
            uint2 h, l;
            split4(rb[i], h, l);
            *(uint2*)(smem + BHI_OFF + boffb + i * 8) = h;
            *(uint2*)(smem + BLO_OFF + boffb + i * 8) = l;
        }
        __syncthreads();

        // prefetch next chunk
        if (c + 1 < NCH) {
            int ko = (c + 1) * TKC;
#pragma unroll
            for (int i = 0; i < 4; i++)
                ra[i] = av ? *(const float4*)(arow_p + ko + 4 * i)
                           : make_float4(0.f, 0.f, 0.f, 0.f);
#pragma unroll
            for (int i = 0; i < 2; i++)
                rb[i] = *(const float4*)(brow_p + ko + 4 * i);
        }

        // compute: 2 k16-steps per chunk
#pragma unroll
        for (int ks = 0; ks < 2; ks++) {
            uint32_t ah0[4], ah1[4], al0[4], al1[4];
            uint32_t aad = a_ld + ks * 32;
            LDSM4(ah0, aad);
            LDSM4(ah1, aad + 16 * SROW * 2);
            LDSM4(al0, aad + (ALO_OFF - AHI_OFF));
            LDSM4(al1, aad + (ALO_OFF - AHI_OFF) + 16 * SROW * 2);
#pragma unroll
            for (int np = 0; np < 2; np++) {
                uint32_t bh[4], bl[4];
                uint32_t bad = b_ld + ks * 32 + np * 16 * SROW * 2;
                LDSM4(bh, bad);
                LDSM4(bl, bad + (BLO_OFF - BHI_OFF));

                MMA16816(acc[0][np * 2 + 0], ah0, bh[0], bh[1]);
                MMA16816(acc[0][np * 2 + 0], al0, bh[0], bh[1]);
                MMA16816(acc[0][np * 2 + 0], ah0, bl[0], bl[1]);
                MMA16816(acc[0][np * 2 + 1], ah0, bh[2], bh[3]);
                MMA16816(acc[0][np * 2 + 1], al0, bh[2], bh[3]);
                MMA16816(acc[0][np * 2 + 1], ah0, bl[2], bl[3]);

                MMA16816(acc[1][np * 2 + 0], ah1, bh[0], bh[1]);
                MMA16816(acc[1][np * 2 + 0], al1, bh[0], bh[1]);
                MMA16816(acc[1][np * 2 + 0], ah1, bl[0], bl[1]);
                MMA16816(acc[1][np * 2 + 1], ah1, bh[2], bh[3]);
                MMA16816(acc[1][np * 2 + 1], al1, bh[2], bh[3]);
                MMA16816(acc[1][np * 2 + 1], ah1, bl[2], bl[3]);
            }
        }
        __syncthreads();
    }

    // epilogue
    float* Cbuf = PH1 ? g_h : g_yp;
    int g = lane >> 2, t4 = lane & 3;
#pragma unroll
    for (int mt = 0; mt < 2; mt++) {
        int mr = m0 + warp_m * 32 + mt * 16 + g;
#pragma unroll
        for (int nt = 0; nt < 4; nt++) {
            int col = n0 + warp_n * 32 + nt * 8 + 2 * t4;
            float2 v0, v1;
            v0.x = acc[mt][nt][0]; v0.y = acc[mt][nt][1];
            v1.x = acc[mt][nt][2]; v1.y = acc[mt][nt][3];
            if (PH1) {
                v0.x = fmaxf(v0.x, 0.f); v0.x *= v0.x;
                v0.y = fmaxf(v0.y, 0.f); v0.y *= v0.y;
                v1.x = fmaxf(v1.x, 0.f); v1.x *= v1.x;
                v1.y = fmaxf(v1.y, 0.f); v1.y *= v1.y;
            }
            if (mr < count)
                *(float2*)(Cbuf + (size_t)(base + mr) * ND + col) = v0;
            if (mr + 8 < count)
                *(float2*)(Cbuf + (size_t)(base + mr + 8) * ND + col) = v1;
        }
    }
}

// ---------------- combine ----------------------------------------------------
__global__ void combine_kernel(float* __restrict__ out, int out_size) {
    const int nv = DDIM / 4;
    int t = blockIdx.x * blockDim.x + threadIdx.x;
    if (t < NTOK * nv) {
        int n = t / nv, dv = t % nv;
        int s0 = g_slotof[2 * n], s1 = g_slotof[2 * n + 1];
        float w0 = g_ew[2 * n], w1 = g_ew[2 * n + 1];
        const float4* yp = (const float4*)g_yp;
        float4 a = yp[(size_t)s0 * nv + dv];
        float4 b = yp[(size_t)s1 * nv + dv];
        float4 r;
        r.x = w0 * a.x + w1 * b.x;
        r.y = w0 * a.y + w1 * b.y;
        r.z = w0 * a.z + w1 * b.z;
        r.w = w0 * a.w + w1 * b.w;
        ((float4*)out)[t] = r;
    }
    if (t == 0) {
        for (int idx = NTOK * DDIM; idx < out_size; idx++) out[idx] = g_loss;
    }
}

// ---------------- launch -----------------------------------------------------
extern "C" void kernel_launch(void* const* d_in, const int* in_sizes, int n_in,
                              void* d_out, int out_size) {
    const float* x   = (const float*)d_in[0];
    const float* wg  = (const float*)d_in[1];
    const float* wfc = (const float*)d_in[2];
    const float* wpj = (const float*)d_in[3];
    float* out = (float*)d_out;

    init_kernel<<<1, 32>>>();
    gating_kernel<<<NTOK / 4, 128>>>(x, wg);
    prefix_kernel<<<1, 32>>>();
    scatter_kernel<<<(NSLOT + 255) / 256, 256>>>();

    dim3 g1(HDIM / TN, NTOK / TM, NEXP);   // 64 x 32 x 8
    gemm_mma<DDIM, HDIM, true><<<g1, 256>>>(x, wfc);

    dim3 g2(DDIM / TN, NTOK / TM, NEXP);   // 16 x 32 x 8
    gemm_mma<HDIM, DDIM, false><<<g2, 256>>>(x, wpj);

    combine_kernel<<<(NTOK * DDIM / 4 + 255) / 256, 256>>>(out, out_size);
}

// round 8
// speedup vs baseline: 2.3613x; 1.6589x over previous
#include <cuda_runtime.h>
#include <cuda_bf16.h>
#include <cstdint>

// Problem constants (B=2, T=2048 -> N=4096 tokens)
#define NTOK 4096
#define DDIM 1024
#define HDIM 4096
#define NEXP 8
#define NSLOT (NTOK * 2)

// ---------------- scratch (static device globals; no allocation) ------------
__device__ __nv_bfloat16 g_xhi[(size_t)NTOK * DDIM];
__device__ __nv_bfloat16 g_xlo[(size_t)NTOK * DDIM];
__device__ __nv_bfloat16 g_fchi[(size_t)NEXP * HDIM * DDIM];
__device__ __nv_bfloat16 g_fclo[(size_t)NEXP * HDIM * DDIM];
__device__ __nv_bfloat16 g_pjhi[(size_t)NEXP * DDIM * HDIM];
__device__ __nv_bfloat16 g_pjlo[(size_t)NEXP * DDIM * HDIM];
__device__ __nv_bfloat16 g_hhi[(size_t)NSLOT * HDIM];
__device__ __nv_bfloat16 g_hlo[(size_t)NSLOT * HDIM];
__device__ float g_yp[(size_t)NSLOT * DDIM];
__device__ int   g_eidx[NSLOT];
__device__ float g_ew[NSLOT];
__device__ int   g_pos[NSLOT];
__device__ int   g_slotof[NSLOT];
__device__ int   g_perm[NSLOT];
__device__ int   g_cnt[NEXP];
__device__ int   g_base[NEXP];
__device__ float g_sump[NEXP];
__device__ float g_loss;

// ---------------- helpers ----------------------------------------------------
__device__ __forceinline__ uint32_t smem_u32(const void* p) {
    uint32_t a;
    asm("{ .reg .u64 t; cvta.to.shared.u64 t, %1; cvt.u32.u64 %0, t; }"
        : "=r"(a) : "l"(p));
    return a;
}

// pack two fp32 -> bf16x2 (x -> low half, y -> high half)
__device__ __forceinline__ uint32_t pack2(float x, float y) {
    uint32_t r;
    asm("cvt.rn.bf16x2.f32 %0, %1, %2;" : "=r"(r) : "f"(y), "f"(x));
    return r;
}

__device__ __forceinline__ void split2(float x, float y, uint32_t& hi, uint32_t& lo) {
    hi = pack2(x, y);
    float hx = __uint_as_float(hi << 16);
    float hy = __uint_as_float(hi & 0xFFFF0000u);
    lo = pack2(x - hx, y - hy);
}

// ---------------- precision-split conversion ---------------------------------
__global__ void convert_kernel(const float* __restrict__ src,
                               __nv_bfloat16* __restrict__ hi,
                               __nv_bfloat16* __restrict__ lo, int n4) {
    int i = blockIdx.x * blockDim.x + threadIdx.x;
    int stride = gridDim.x * blockDim.x;
    for (; i < n4; i += stride) {
        float4 v = ((const float4*)src)[i];
        uint32_t h0, l0, h1, l1;
        split2(v.x, v.y, h0, l0);
        split2(v.z, v.w, h1, l1);
        ((uint2*)hi)[i] = make_uint2(h0, h1);
        ((uint2*)lo)[i] = make_uint2(l0, l1);
    }
}

// ---------------- init -------------------------------------------------------
__global__ void init_kernel() {
    int t = threadIdx.x;
    if (t < NEXP) { g_cnt[t] = 0; g_sump[t] = 0.0f; }
}

// ---------------- gating: 1 warp per token -----------------------------------
__global__ void gating_kernel(const float* __restrict__ x,
                              const float* __restrict__ wg) {
    int warp = (blockIdx.x * blockDim.x + threadIdx.x) >> 5;
    int lane = threadIdx.x & 31;
    if (warp >= NTOK) return;
    const float* xr = x + (size_t)warp * DDIM;

    float acc[NEXP];
#pragma unroll
    for (int e = 0; e < NEXP; e++) acc[e] = 0.0f;

    for (int d = lane; d < DDIM; d += 32) {
        float xv = xr[d];
#pragma unroll
        for (int e = 0; e < NEXP; e++) acc[e] += xv * wg[e * DDIM + d];
    }
#pragma unroll
    for (int e = 0; e < NEXP; e++) {
#pragma unroll
        for (int o = 16; o > 0; o >>= 1)
            acc[e] += __shfl_xor_sync(0xFFFFFFFFu, acc[e], o);
    }

    if (lane == 0) {
        float mx = acc[0];
#pragma unroll
        for (int e = 1; e < NEXP; e++) mx = fmaxf(mx, acc[e]);
        float p[NEXP], s = 0.0f;
#pragma unroll
        for (int e = 0; e < NEXP; e++) { p[e] = __expf(acc[e] - mx); s += p[e]; }
        float inv = 1.0f / s;
#pragma unroll
        for (int e = 0; e < NEXP; e++) p[e] *= inv;

#pragma unroll
        for (int e = 0; e < NEXP; e++) atomicAdd(&g_sump[e], p[e]);

        int i0 = 0;
#pragma unroll
        for (int e = 1; e < NEXP; e++) if (p[e] > p[i0]) i0 = e;
        int i1 = (i0 == 0) ? 1 : 0;
#pragma unroll
        for (int e = 0; e < NEXP; e++) if (e != i0 && p[e] > p[i1]) i1 = e;

        float w0 = p[i0], w1 = p[i1];
        float rinv = 1.0f / (w0 + w1);
        w0 *= rinv; w1 *= rinv;

        g_eidx[2 * warp + 0] = i0;
        g_eidx[2 * warp + 1] = i1;
        g_ew[2 * warp + 0] = w0;
        g_ew[2 * warp + 1] = w1;
        g_pos[2 * warp + 0] = atomicAdd(&g_cnt[i0], 1);
        g_pos[2 * warp + 1] = atomicAdd(&g_cnt[i1], 1);
    }
}

// ---------------- prefix + balance loss --------------------------------------
__global__ void prefix_kernel() {
    if (threadIdx.x == 0) {
        int b = 0;
        float loss = 0.0f;
        for (int e = 0; e < NEXP; e++) {
            g_base[e] = b;
            b += g_cnt[e];
            loss += g_sump[e] * (float)g_cnt[e];
        }
        g_loss = loss * (float)NEXP / ((float)NTOK * (float)NTOK);
    }
}

// ---------------- scatter ----------------------------------------------------
__global__ void scatter_kernel() {
    int t = blockIdx.x * blockDim.x + threadIdx.x;
    if (t < NSLOT) {
        int e = g_eidx[t];
        int slot = g_base[e] + g_pos[t];
        g_slotof[t] = slot;
        g_perm[slot] = t >> 1;
    }
}

// ---------------- bf16x3 mma.sync grouped GEMM, cp.async pipelined -----------
// D[m,n] = sum_k A[m,k]*B[n,k] with A,B pre-split into bf16 hi/lo.
// acc += Ahi*Bhi + Alo*Bhi + Ahi*Blo.  CTA tile 128x64, K chunk 32,
// 8 warps 4(M)x2(N), warp tile 32x32.  Double-buffered SMEM via cp.async.
#define TM 128
#define TN 64
#define TKC 32
#define SROW 40                    // halves per smem row (80B, conflict-free)
#define A_HI 0
#define A_LO 10240                 // 128*80
#define B_HI 20480
#define B_LO 25600                 // +64*80
#define SSTG 30720
#define SMEM_DYN (2 * SSTG)        // 61440

#define CPA16(dst, src, sz) \
    asm volatile("cp.async.cg.shared.global [%0], [%1], 16, %2;" \
                 :: "r"(dst), "l"(src), "r"(sz))
#define CPA_COMMIT() asm volatile("cp.async.commit_group;" ::: "memory")
#define CPA_WAIT1() asm volatile("cp.async.wait_group 1;" ::: "memory")
#define CPA_WAIT0() asm volatile("cp.async.wait_group 0;" ::: "memory")

#define LDSM4(r, addr) \
    asm volatile("ldmatrix.sync.aligned.m8n8.x4.shared.b16 {%0,%1,%2,%3}, [%4];" \
                 : "=r"((r)[0]), "=r"((r)[1]), "=r"((r)[2]), "=r"((r)[3]) \
                 : "r"(addr))

#define MMA16816(c, a, b0_, b1_) \
    asm volatile("mma.sync.aligned.m16n8k16.row.col.f32.bf16.bf16.f32 " \
                 "{%0,%1,%2,%3}, {%4,%5,%6,%7}, {%8,%9}, {%0,%1,%2,%3};" \
                 : "+f"((c)[0]), "+f"((c)[1]), "+f"((c)[2]), "+f"((c)[3]) \
                 : "r"((a)[0]), "r"((a)[1]), "r"((a)[2]), "r"((a)[3]), \
                   "r"(b0_), "r"(b1_))

template <int KD, int ND, bool PH1>
__global__ __launch_bounds__(256)
void gemm_bf16(const __nv_bfloat16* __restrict__ Ahi_,
               const __nv_bfloat16* __restrict__ Alo_,
               const __nv_bfloat16* __restrict__ Bhi_,
               const __nv_bfloat16* __restrict__ Blo_) {
    extern __shared__ __align__(16) unsigned char smem[];
    int e = blockIdx.z;
    int count = g_cnt[e];
    int m0 = blockIdx.y * TM;
    if (m0 >= count) return;
    int n0 = blockIdx.x * TN;
    int base = g_base[e];

    const __nv_bfloat16* Bhi = Bhi_ + (size_t)e * KD * ND;
    const __nv_bfloat16* Blo = Blo_ + (size_t)e * KD * ND;

    int tid = threadIdx.x;
    int lane = tid & 31;
    int wid = tid >> 5;
    int warp_m = wid & 3;
    int warp_n = wid >> 2;
    uint32_t sb = smem_u32(smem);

    // --- cp.async loader mapping ---
    int arow = tid >> 1;                 // A tile row 0..127
    int ahalf = tid & 1;                 // which 32B half of the 64B row
    int browi = tid >> 2;                // B tile row 0..63
    int bq = tid & 3;                    // 16B unit 0..3

    int am = m0 + arow;
    bool av = am < count;
    int gidx = 0;
    if (av) gidx = PH1 ? g_perm[base + am] : (base + am);
    uint32_t asz = av ? 16u : 0u;
    const __nv_bfloat16* a_hi_src = Ahi_ + (size_t)gidx * KD + ahalf * 16;
    const __nv_bfloat16* a_lo_src = Alo_ + (size_t)gidx * KD + ahalf * 16;
    const __nv_bfloat16* b_hi_src = Bhi + (size_t)(n0 + browi) * KD + bq * 8;
    const __nv_bfloat16* b_lo_src = Blo + (size_t)(n0 + browi) * KD + bq * 8;

    uint32_t a_dst = sb + arow * (SROW * 2) + ahalf * 32;
    uint32_t b_dst = sb + browi * (SROW * 2) + bq * 16;

    // --- ldmatrix lane addresses (relative to stage base) ---
    uint32_t arow_l = (uint32_t)(warp_m * 32 + (lane & 7) + ((lane >> 3) & 1) * 8);
    uint32_t akoff = (uint32_t)((lane >> 4) * 8);
    uint32_t a_ld = sb + (arow_l * SROW + akoff) * 2;
    uint32_t brow_l = (uint32_t)(warp_n * 32 + (lane & 7) + (lane >> 4) * 8);
    uint32_t bkoff = (uint32_t)(((lane >> 3) & 1) * 8);
    uint32_t b_ld = sb + B_HI + (brow_l * SROW + bkoff) * 2;

    float acc[2][4][4];
#pragma unroll
    for (int i = 0; i < 2; i++)
#pragma unroll
        for (int j = 0; j < 4; j++)
#pragma unroll
            for (int q = 0; q < 4; q++) acc[i][j][q] = 0.0f;

    auto issue = [&](int s, int k0) {
        uint32_t ad = a_dst + s * SSTG;
        CPA16(ad + A_HI,      a_hi_src + k0,     asz);
        CPA16(ad + A_HI + 16, a_hi_src + k0 + 8, asz);
        CPA16(ad + A_LO,      a_lo_src + k0,     asz);
        CPA16(ad + A_LO + 16, a_lo_src + k0 + 8, asz);
        uint32_t bd = b_dst + s * SSTG;
        CPA16(bd + B_HI, b_hi_src + k0, 16u);
        CPA16(bd + B_LO, b_lo_src + k0, 16u);
    };

    const int NCH = KD / TKC;
    issue(0, 0);
    CPA_COMMIT();

    for (int c = 0; c < NCH; c++) {
        if (c + 1 < NCH) {
            issue((c + 1) & 1, (c + 1) * TKC);
            CPA_COMMIT();
            CPA_WAIT1();
        } else {
            CPA_WAIT0();
        }
        __syncthreads();

        int s = c & 1;
        uint32_t abase = a_ld + s * SSTG;
        uint32_t bbase = b_ld + s * SSTG;
#pragma unroll
        for (int ks = 0; ks < 2; ks++) {
            uint32_t ah0[4], ah1[4], al0[4], al1[4];
            uint32_t aad = abase + ks * 32;
            LDSM4(ah0, aad);
            LDSM4(ah1, aad + 16 * SROW * 2);
            LDSM4(al0, aad + A_LO);
            LDSM4(al1, aad + A_LO + 16 * SROW * 2);
#pragma unroll
            for (int np = 0; np < 2; np++) {
                uint32_t bh[4], bl[4];
                uint32_t bad = bbase + ks * 32 + np * 16 * SROW * 2;
                LDSM4(bh, bad);
                LDSM4(bl, bad + (B_LO - B_HI));

                MMA16816(acc[0][np * 2 + 0], ah0, bh[0], bh[1]);
                MMA16816(acc[0][np * 2 + 0], al0, bh[0], bh[1]);
                MMA16816(acc[0][np * 2 + 0], ah0, bl[0], bl[1]);
                MMA16816(acc[0][np * 2 + 1], ah0, bh[2], bh[3]);
                MMA16816(acc[0][np * 2 + 1], al0, bh[2], bh[3]);
                MMA16816(acc[0][np * 2 + 1], ah0, bl[2], bl[3]);

                MMA16816(acc[1][np * 2 + 0], ah1, bh[0], bh[1]);
                MMA16816(acc[1][np * 2 + 0], al1, bh[0], bh[1]);
                MMA16816(acc[1][np * 2 + 0], ah1, bl[0], bl[1]);
                MMA16816(acc[1][np * 2 + 1], ah1, bh[2], bh[3]);
                MMA16816(acc[1][np * 2 + 1], al1, bh[2], bh[3]);
                MMA16816(acc[1][np * 2 + 1], ah1, bl[2], bl[3]);
            }
        }
        __syncthreads();
    }

    // epilogue
    int g = lane >> 2, t4 = lane & 3;
#pragma unroll
    for (int mt = 0; mt < 2; mt++) {
        int mr = m0 + warp_m * 32 + mt * 16 + g;
#pragma unroll
        for (int nt = 0; nt < 4; nt++) {
            int col = n0 + warp_n * 32 + nt * 8 + 2 * t4;
            float2 v0, v1;
            v0.x = acc[mt][nt][0]; v0.y = acc[mt][nt][1];
            v1.x = acc[mt][nt][2]; v1.y = acc[mt][nt][3];
            if (PH1) {
                v0.x = fmaxf(v0.x, 0.f); v0.x *= v0.x;
                v0.y = fmaxf(v0.y, 0.f); v0.y *= v0.y;
                v1.x = fmaxf(v1.x, 0.f); v1.x *= v1.x;
                v1.y = fmaxf(v1.y, 0.f); v1.y *= v1.y;
                uint32_t h, l;
                if (mr < count) {
                    size_t o = (size_t)(base + mr) * ND + col;
                    split2(v0.x, v0.y, h, l);
                    *(uint32_t*)(g_hhi + o) = h;
                    *(uint32_t*)(g_hlo + o) = l;
                }
                if (mr + 8 < count) {
                    size_t o = (size_t)(base + mr + 8) * ND + col;
                    split2(v1.x, v1.y, h, l);
                    *(uint32_t*)(g_hhi + o) = h;
                    *(uint32_t*)(g_hlo + o) = l;
                }
            } else {
                if (mr < count)
                    *(float2*)(g_yp + (size_t)(base + mr) * ND + col) = v0;
                if (mr + 8 < count)
                    *(float2*)(g_yp + (size_t)(base + mr + 8) * ND + col) = v1;
            }
        }
    }
}

// ---------------- combine ----------------------------------------------------
__global__ void combine_kernel(float* __restrict__ out, int out_size) {
    const int nv = DDIM / 4;
    int t = blockIdx.x * blockDim.x + threadIdx.x;
    if (t < NTOK * nv) {
        int n = t / nv, dv = t % nv;
        int s0 = g_slotof[2 * n], s1 = g_slotof[2 * n + 1];
        float w0 = g_ew[2 * n], w1 = g_ew[2 * n + 1];
        const float4* yp = (const float4*)g_yp;
        float4 a = yp[(size_t)s0 * nv + dv];
        float4 b = yp[(size_t)s1 * nv + dv];
        float4 r;
        r.x = w0 * a.x + w1 * b.x;
        r.y = w0 * a.y + w1 * b.y;
        r.z = w0 * a.z + w1 * b.z;
        r.w = w0 * a.w + w1 * b.w;
        ((float4*)out)[t] = r;
    }
    if (t == 0) {
        for (int idx = NTOK * DDIM; idx < out_size; idx++) out[idx] = g_loss;
    }
}

// ---------------- launch -----------------------------------------------------
extern "C" void kernel_launch(void* const* d_in, const int* in_sizes, int n_in,
                              void* d_out, int out_size) {
    const float* x   = (const float*)d_in[0];
    const float* wg  = (const float*)d_in[1];
    const float* wfc = (const float*)d_in[2];
    const float* wpj = (const float*)d_in[3];
    float* out = (float*)d_out;

    cudaFuncSetAttribute(gemm_bf16<DDIM, HDIM, true>,
                         cudaFuncAttributeMaxDynamicSharedMemorySize, SMEM_DYN);
    cudaFuncSetAttribute(gemm_bf16<HDIM, DDIM, false>,
                         cudaFuncAttributeMaxDynamicSharedMemorySize, SMEM_DYN);

    __nv_bfloat16 *xhi, *xlo, *fchi, *fclo, *pjhi, *pjlo, *hhi, *hlo;
    cudaGetSymbolAddress((void**)&xhi, g_xhi);
    cudaGetSymbolAddress((void**)&xlo, g_xlo);
    cudaGetSymbolAddress((void**)&fchi, g_fchi);
    cudaGetSymbolAddress((void**)&fclo, g_fclo);
    cudaGetSymbolAddress((void**)&pjhi, g_pjhi);
    cudaGetSymbolAddress((void**)&pjlo, g_pjlo);
    cudaGetSymbolAddress((void**)&hhi, g_hhi);
    cudaGetSymbolAddress((void**)&hlo, g_hlo);

    init_kernel<<<1, 32>>>();
    convert_kernel<<<1184, 256>>>(x, xhi, xlo, NTOK * DDIM / 4);
    convert_kernel<<<1184, 256>>>(wfc, fchi, fclo, NEXP * HDIM * DDIM / 4);
    convert_kernel<<<1184, 256>>>(wpj, pjhi, pjlo, NEXP * DDIM * HDIM / 4);
    gating_kernel<<<NTOK / 4, 128>>>(x, wg);
    prefix_kernel<<<1, 32>>>();
    scatter_kernel<<<(NSLOT + 255) / 256, 256>>>();

    dim3 g1(HDIM / TN, NSLOT / TM, NEXP);   // 64 x 64 x 8
    gemm_bf16<DDIM, HDIM, true><<<g1, 256, SMEM_DYN>>>(xhi, xlo, fchi, fclo);

    dim3 g2(DDIM / TN, NSLOT / TM, NEXP);   // 16 x 64 x 8
    gemm_bf16<HDIM, DDIM, false><<<g2, 256, SMEM_DYN>>>(hhi, hlo, pjhi, pjlo);

    combine_kernel<<<(NTOK * DDIM / 4 + 255) / 256, 256>>>(out, out_size);
}